// round 1
// baseline (speedup 1.0000x reference)
#include <cuda_runtime.h>
#include <math.h>

#define Bb 8
#define Nn 2046
#define Dd 128
#define Jj 128
#define Ll 2
#define Cc 2048           // N + 2
#define BC (Bb*Cc)        // 16384
#define BN (Bb*Nn)        // 16368

// ---------------- device scratch (no allocation allowed) ----------------
__device__ float g_feats0[BC*Dd];
__device__ float g_feats1[BC*Dd];
__device__ float g_v[BC*Dd];
__device__ float g_seq[BC*Dd];
__device__ float g_weighted[BC*Dd];
__device__ float g_attnout[BC*Dd];
__device__ float g_qs[BC];
__device__ float g_ks[BC];
__device__ float g_uq[Dd];
__device__ float g_uk[Dd];
__device__ float g_c[2];

// ---------------- copy ops into feats rows [0,N) ----------------
__global__ void copy_ops_kernel(const float* __restrict__ ops, float* __restrict__ feats)
{
    int idx = blockIdx.x * 256 + threadIdx.x;   // BN*D = 2095104 = 8184*256
    int b = idx / (Nn*Dd);
    int rem = idx - b*(Nn*Dd);
    feats[(size_t)b*Cc*Dd + rem] = ops[idx];
}

__global__ void copyout_kernel(const float* __restrict__ feats, float* __restrict__ out)
{
    size_t idx = (size_t)blockIdx.x * 256 + threadIdx.x;   // BC*D = 2097152 = 8192*256
    out[idx] = feats[idx];
}

// ---------------- fused begin/end: gather-avg + [D,D] matvec ----------------
// grid (B, 2): y==0 -> begin (row N), y==1 -> end (row N+1)
__global__ void __launch_bounds__(128) begin_end_kernel(
    const float* __restrict__ src,   // [B, C, D]
    const int* __restrict__ bidx, const int* __restrict__ eidx,
    const float* __restrict__ Wb, const float* __restrict__ bb,
    const float* __restrict__ We, const float* __restrict__ be,
    float* __restrict__ dst)         // [B, C, D]; writes row N+which
{
    int b = blockIdx.x, which = blockIdx.y, tx = threadIdx.x;
    const int* idx = which ? eidx : bidx;
    const float* W = which ? We : Wb;
    const float* bias = which ? be : bb;
    __shared__ float avg[128];
    float s = 0.f;
    #pragma unroll 8
    for (int j = 0; j < Jj; ++j) {
        int r = idx[b*Jj + j];
        s += src[((size_t)b*Cc + r)*Dd + tx];
    }
    avg[tx] = s * (1.f/Jj);
    __syncthreads();
    float o = 0.f;
    #pragma unroll 8
    for (int dd = 0; dd < Dd; ++dd)
        o += avg[dd] * W[dd*Dd + tx];
    dst[((size_t)b*Cc + Nn + which)*Dd + tx] = o + bias[tx];
}

// ---------------- precompute uq, uk, cq, ck for one layer ----------------
__global__ void __launch_bounds__(128) precompute_kernel(
    const float* __restrict__ aw,   // attn_w_w + l*128*384
    const float* __restrict__ ab,   // attn_w_b + l*384
    const float* __restrict__ sw,   // score_w + l*256
    const float* __restrict__ sb,   // score_b + l
    float* __restrict__ uq, float* __restrict__ uk, float* __restrict__ cv)
{
    int d = threadIdx.x;
    float s1 = 0.f, s2 = 0.f;
    #pragma unroll 8
    for (int e = 0; e < 128; ++e) {
        s1 += aw[d*384 + e]       * sw[e];
        s2 += aw[d*384 + 128 + e] * sw[128 + e];
    }
    uq[d] = s1; uk[d] = s2;
    if (d == 0) {
        float c1 = 0.f, c2 = 0.f;
        for (int e = 0; e < 128; ++e) { c1 += ab[e]*sw[e]; c2 += ab[128+e]*sw[128+e]; }
        cv[0] = c1;
        cv[1] = c2 + sb[0];   // fold score bias into ks const
    }
}

// ---------------- qs/ks per row: one warp per row ----------------
__global__ void __launch_bounds__(256) qsks_kernel(
    const float* __restrict__ feats,
    const float* __restrict__ uq, const float* __restrict__ uk,
    const float* __restrict__ cv,
    float* __restrict__ qs, float* __restrict__ ks)
{
    int warp = threadIdx.x >> 5;
    int lane = threadIdx.x & 31;
    int m = blockIdx.x * 8 + warp;    // grid = BC/8
    float4 f = ((const float4*)(feats + (size_t)m*Dd))[lane];
    float4 q4 = ((const float4*)uq)[lane];
    float4 k4 = ((const float4*)uk)[lane];
    float dq = f.x*q4.x + f.y*q4.y + f.z*q4.z + f.w*q4.w;
    float dk = f.x*k4.x + f.y*k4.y + f.z*k4.z + f.w*k4.w;
    #pragma unroll
    for (int off = 16; off; off >>= 1) {
        dq += __shfl_down_sync(0xffffffffu, dq, off);
        dk += __shfl_down_sync(0xffffffffu, dk, off);
    }
    if (lane == 0) { qs[m] = dq + cv[0]; ks[m] = dk + cv[1]; }
}

// ---------------- generic 128-output SGEMM, 3 A-access modes ----------------
// MODE 0: plain rows (A + m*128)
// MODE 1: gather3 (K=384): seg0=self, seg1=pred, seg2=succ from feats via relations
// MODE 2: concat2 (K=256): seg0=A, seg1=A2
template<int MODE, int KTOT>
__global__ void __launch_bounds__(128) gemm128_kernel(
    const float* __restrict__ A,
    const float* __restrict__ A2,
    const float* __restrict__ W, int ws,
    const float* __restrict__ bias,
    float* __restrict__ out,
    const int* __restrict__ relations,
    int M)
{
    __shared__ float As[32*36];     // transposed: As[kk*36 + i]
    __shared__ float Ws[32*128];
    __shared__ int s_src[3][32];
    __shared__ int s_outrow[32];

    int tx = threadIdx.x;
    int m0 = blockIdx.x * 32;

    if (tx < 32) {
        int m = m0 + tx;
        if (MODE == 1) {
            if (m < M) {
                int b = m / Nn;
                int i = m - b*Nn;
                s_src[0][tx] = b*Cc + i;
                int rp = relations[(size_t)(b*Nn + i)*2 + 0];
                int rs = relations[(size_t)(b*Nn + i)*2 + 1];
                s_src[1][tx] = b*Cc + (rp < 0 ? Nn : rp);
                s_src[2][tx] = b*Cc + (rs < 0 ? Nn + 1 : rs);
                s_outrow[tx] = b*Cc + i;
            } else {
                s_src[0][tx] = 0; s_src[1][tx] = 0; s_src[2][tx] = 0;
                s_outrow[tx] = -1;
            }
        } else {
            s_outrow[tx] = (m < M) ? m : -1;
        }
    }
    __syncthreads();

    float acc[32];
    #pragma unroll
    for (int i = 0; i < 32; ++i) acc[i] = 0.f;

    const int NCHUNK = KTOT / 32;
    for (int kc = 0; kc < NCHUNK; ++kc) {
        int k0 = kc * 32;
        // W tile
        #pragma unroll 8
        for (int kk = 0; kk < 32; ++kk)
            Ws[kk*128 + tx] = W[(size_t)(k0 + kk)*ws + tx];
        // A tile (transposed)
        int seg  = k0 >> 7;
        int col0 = k0 & 127;
        #pragma unroll
        for (int r = 0; r < 8; ++r) {
            int idx = tx + 128*r;
            int i  = idx >> 5;
            int kk = idx & 31;
            float v;
            if (MODE == 0) {
                v = A[(size_t)(m0 + i)*128 + col0 + kk];
            } else if (MODE == 1) {
                v = A[(size_t)s_src[seg][i]*128 + col0 + kk];
            } else {
                const float* src = seg ? A2 : A;
                v = src[(size_t)(m0 + i)*128 + col0 + kk];
            }
            As[kk*36 + i] = v;
        }
        __syncthreads();
        const float4* As4 = (const float4*)As;
        #pragma unroll 4
        for (int kk = 0; kk < 32; ++kk) {
            float w = Ws[kk*128 + tx];
            #pragma unroll
            for (int i4 = 0; i4 < 8; ++i4) {
                float4 a = As4[kk*9 + i4];
                acc[i4*4+0] += a.x * w;
                acc[i4*4+1] += a.y * w;
                acc[i4*4+2] += a.z * w;
                acc[i4*4+3] += a.w * w;
            }
        }
        __syncthreads();
    }
    float bv = bias[tx];
    #pragma unroll
    for (int i = 0; i < 32; ++i) {
        int orow = s_outrow[i];
        if (orow >= 0) out[(size_t)orow*128 + tx] = acc[i] + bv;
    }
}

// ---------------- fused masked GAT attention, flash-style ----------------
// grid (C/16, B), block 128. weighted[b,i,:] = softmax_j(lrelu(qs_i+ks_j)*mask) @ v
__global__ void __launch_bounds__(128) attn_kernel(
    const float* __restrict__ v,
    const float* __restrict__ qs, const float* __restrict__ ks,
    const float* __restrict__ mask,
    float* __restrict__ weighted)
{
    __shared__ float vs[64*128];
    __shared__ float ps[64*20];       // ps[jj*20 + i], stride 20 for aligned float4
    __shared__ float s_qs[16], s_ks[64];
    __shared__ float s_m[16], s_sum[16], s_scale[16];

    int b  = blockIdx.y;
    int i0 = blockIdx.x * 16;
    int tx = threadIdx.x;

    if (tx < 16) {
        s_qs[tx]  = qs[b*Cc + i0 + tx];
        s_m[tx]   = -1e30f;
        s_sum[tx] = 0.f;
    }

    float acc[16];
    #pragma unroll
    for (int i = 0; i < 16; ++i) acc[i] = 0.f;

    for (int j0 = 0; j0 < Cc; j0 += 64) {
        if (tx < 64) s_ks[tx] = ks[b*Cc + j0 + tx];
        #pragma unroll 8
        for (int jj = 0; jj < 64; ++jj)
            vs[jj*128 + tx] = v[((size_t)b*Cc + j0 + jj)*128 + tx];
        __syncthreads();

        // logits -> ps (mask multiplies the leaky-relu score, pre-softmax)
        #pragma unroll
        for (int r = 0; r < 8; ++r) {
            int e  = tx + 128*r;
            int i  = e >> 6;
            int jj = e & 63;
            int gi = i0 + i;
            int j  = j0 + jj;
            float mval;
            if (gi < Nn && j < Nn) mval = mask[((size_t)b*Nn + gi)*Nn + j];
            else                   mval = (gi == j) ? 1.f : 0.f;
            float s  = s_qs[i] + s_ks[jj];
            float lr = s > 0.f ? s : 0.01f * s;
            ps[jj*20 + i] = lr * mval;
        }
        __syncthreads();

        if (tx < 16) {
            float tm = -1e30f;
            #pragma unroll 8
            for (int jj = 0; jj < 64; ++jj) tm = fmaxf(tm, ps[jj*20 + tx]);
            float om = s_m[tx];
            float nm = fmaxf(om, tm);
            s_scale[tx] = __expf(om - nm);
            s_m[tx] = nm;
        }
        __syncthreads();

        #pragma unroll
        for (int r = 0; r < 8; ++r) {
            int e  = tx + 128*r;
            int i  = e >> 6;
            int jj = e & 63;
            ps[jj*20 + i] = __expf(ps[jj*20 + i] - s_m[i]);
        }
        __syncthreads();

        if (tx < 16) {
            float ss = 0.f;
            #pragma unroll 8
            for (int jj = 0; jj < 64; ++jj) ss += ps[jj*20 + tx];
            s_sum[tx] = s_sum[tx]*s_scale[tx] + ss;
        }

        #pragma unroll
        for (int i = 0; i < 16; ++i) acc[i] *= s_scale[i];
        #pragma unroll 2
        for (int jj = 0; jj < 64; ++jj) {
            float vv = vs[jj*128 + tx];
            const float4* p4 = (const float4*)(ps + jj*20);
            float4 a;
            a = p4[0]; acc[0] += a.x*vv; acc[1] += a.y*vv; acc[2]  += a.z*vv; acc[3]  += a.w*vv;
            a = p4[1]; acc[4] += a.x*vv; acc[5] += a.y*vv; acc[6]  += a.z*vv; acc[7]  += a.w*vv;
            a = p4[2]; acc[8] += a.x*vv; acc[9] += a.y*vv; acc[10] += a.z*vv; acc[11] += a.w*vv;
            a = p4[3]; acc[12]+= a.x*vv; acc[13]+= a.y*vv; acc[14] += a.z*vv; acc[15] += a.w*vv;
        }
        __syncthreads();
    }

    #pragma unroll
    for (int i = 0; i < 16; ++i)
        weighted[((size_t)b*Cc + i0 + i)*128 + tx] = acc[i] / s_sum[i];
}

// ---------------- mean over C rows ----------------
__global__ void __launch_bounds__(128) mean_kernel(const float* __restrict__ feats,
                                                   float* __restrict__ out)
{
    int b = blockIdx.x, tx = threadIdx.x;
    float s = 0.f;
    #pragma unroll 8
    for (int i = 0; i < Cc; ++i)
        s += feats[((size_t)b*Cc + i)*128 + tx];
    out[b*128 + tx] = s * (1.f/Cc);
}

// ---------------- host launcher ----------------
extern "C" void kernel_launch(void* const* d_in, const int* in_sizes, int n_in,
                              void* d_out, int out_size)
{
    const float* ops        = (const float*)d_in[0];
    const float* mask       = (const float*)d_in[1];
    const int*   relations  = (const int*)  d_in[2];
    const int*   begins     = (const int*)  d_in[3];
    const int*   ends       = (const int*)  d_in[4];
    const float* init_bp_w  = (const float*)d_in[5];
    const float* init_bp_b  = (const float*)d_in[6];
    const float* init_ep_w  = (const float*)d_in[7];
    const float* init_ep_b  = (const float*)d_in[8];
    const float* be_bp_w    = (const float*)d_in[9];
    const float* be_bp_b    = (const float*)d_in[10];
    const float* be_ep_w    = (const float*)d_in[11];
    const float* be_ep_b    = (const float*)d_in[12];
    const float* seq_mix_w  = (const float*)d_in[13];
    const float* seq_mix_b  = (const float*)d_in[14];
    const float* attn_w_w   = (const float*)d_in[15];
    const float* attn_w_b   = (const float*)d_in[16];
    const float* score_w    = (const float*)d_in[17];
    const float* score_b    = (const float*)d_in[18];
    const float* attn_out_w = (const float*)d_in[19];
    const float* attn_out_b = (const float*)d_in[20];
    const float* mix_w      = (const float*)d_in[21];
    const float* mix_b      = (const float*)d_in[22];
    float* out = (float*)d_out;

    float *p_f0, *p_f1, *p_v, *p_seq, *p_wt, *p_ao, *p_qs, *p_ks, *p_uq, *p_uk, *p_c;
    cudaGetSymbolAddress((void**)&p_f0, g_feats0);
    cudaGetSymbolAddress((void**)&p_f1, g_feats1);
    cudaGetSymbolAddress((void**)&p_v,  g_v);
    cudaGetSymbolAddress((void**)&p_seq, g_seq);
    cudaGetSymbolAddress((void**)&p_wt, g_weighted);
    cudaGetSymbolAddress((void**)&p_ao, g_attnout);
    cudaGetSymbolAddress((void**)&p_qs, g_qs);
    cudaGetSymbolAddress((void**)&p_ks, g_ks);
    cudaGetSymbolAddress((void**)&p_uq, g_uq);
    cudaGetSymbolAddress((void**)&p_uk, g_uk);
    cudaGetSymbolAddress((void**)&p_c,  g_c);

    // init: feats0 = [ops; begin; end]
    copy_ops_kernel<<<(BN*Dd)/256, 256>>>(ops, p_f0);
    begin_end_kernel<<<dim3(Bb, 2), 128>>>(p_f0, begins, ends,
                                           init_bp_w, init_bp_b, init_ep_w, init_ep_b,
                                           p_f0);

    for (int l = 0; l < Ll; ++l) {
        float* cur = (l == 0) ? p_f0 : p_f1;
        float* nxt = (l == 0) ? p_f1 : p_f0;

        precompute_kernel<<<1, 128>>>(attn_w_w + (size_t)l*128*384,
                                      attn_w_b + (size_t)l*384,
                                      score_w + (size_t)l*256,
                                      score_b + l,
                                      p_uq, p_uk, p_c);
        qsks_kernel<<<BC/8, 256>>>(cur, p_uq, p_uk, p_c, p_qs, p_ks);

        // v = feats @ Wv + bv  (Wv = attn_w_w[l][:, 256:384])
        gemm128_kernel<0,128><<<BC/32, 128>>>(cur, nullptr,
            attn_w_w + (size_t)l*128*384 + 256, 384,
            attn_w_b + (size_t)l*384 + 256,
            p_v, nullptr, BC);

        // in-layer begin/end -> seq rows N, N+1
        begin_end_kernel<<<dim3(Bb, 2), 128>>>(cur, begins, ends,
            be_bp_w + (size_t)l*128*128, be_bp_b + (size_t)l*128,
            be_ep_w + (size_t)l*128*128, be_ep_b + (size_t)l*128,
            p_seq);

        // mixed = [self, pred, succ] @ seq_mix_w[l] + b  -> seq rows [0, N)
        gemm128_kernel<1,384><<<(BN+31)/32, 128>>>(cur, nullptr,
            seq_mix_w + (size_t)l*384*128, 128,
            seq_mix_b + (size_t)l*128,
            p_seq, relations, BN);

        // fused masked attention -> weighted
        attn_kernel<<<dim3(Cc/16, Bb), 128>>>(p_v, p_qs, p_ks, mask, p_wt);

        // attn_out = weighted @ attn_out_w[l] + b
        gemm128_kernel<0,128><<<BC/32, 128>>>(p_wt, nullptr,
            attn_out_w + (size_t)l*128*128, 128,
            attn_out_b + (size_t)l*128,
            p_ao, nullptr, BC);

        // feats_next = [seq_feats, attn_out] @ mix_w[l] + b
        gemm128_kernel<2,256><<<BC/32, 128>>>(p_seq, p_ao,
            mix_w + (size_t)l*256*128, 128,
            mix_b + (size_t)l*128,
            nxt, nullptr, BC);
    }

    // outputs: mean [B,D] then feats [B,C,D]   (final feats is g_feats0 after L=2)
    mean_kernel<<<Bb, 128>>>(p_f0, out);
    copyout_kernel<<<(BC*Dd)/256, 256>>>(p_f0, out + Bb*Dd);
}

// round 2
// speedup vs baseline: 1.0692x; 1.0692x over previous
#include <cuda_runtime.h>
#include <math.h>

#define Bb 8
#define Nn 2046
#define Dd 128
#define Jj 128
#define Ll 2
#define Cc 2048           // N + 2
#define BC (Bb*Cc)        // 16384
#define BN (Bb*Nn)        // 16368

// ---------------- device scratch (no allocation allowed) ----------------
__device__ float g_feats0[BC*Dd];
__device__ float g_feats1[BC*Dd];
__device__ float g_v[BC*Dd];
__device__ float g_seq[BC*Dd];
__device__ float g_weighted[BC*Dd];
__device__ float g_attnout[BC*Dd];
__device__ float g_qs[BC];
__device__ float g_ks[BC];
__device__ float g_uq[Dd];
__device__ float g_uk[Dd];
__device__ float g_c[2];
__device__ float g_part[Bb*16*Dd];

// ---------------- copy ops into feats rows [0,N) ----------------
__global__ void copy_ops_kernel(const float* __restrict__ ops, float* __restrict__ feats)
{
    int idx = blockIdx.x * 256 + threadIdx.x;   // BN*D = 2095104 = 8184*256
    int b = idx / (Nn*Dd);
    int rem = idx - b*(Nn*Dd);
    feats[(size_t)b*Cc*Dd + rem] = ops[idx];
}

__global__ void copyout_kernel(const float* __restrict__ feats, float* __restrict__ out)
{
    size_t idx = (size_t)blockIdx.x * 256 + threadIdx.x;   // BC*D = 2097152 = 8192*256
    out[idx] = feats[idx];
}

// ---------------- fused begin/end: gather-avg + [D,D] matvec ----------------
__global__ void __launch_bounds__(128) begin_end_kernel(
    const float* __restrict__ src,   // [B, C, D]
    const int* __restrict__ bidx, const int* __restrict__ eidx,
    const float* __restrict__ Wb, const float* __restrict__ bb,
    const float* __restrict__ We, const float* __restrict__ be,
    float* __restrict__ dst)         // [B, C, D]; writes row N+which
{
    int b = blockIdx.x, which = blockIdx.y, tx = threadIdx.x;
    const int* idx = which ? eidx : bidx;
    const float* W = which ? We : Wb;
    const float* bias = which ? be : bb;
    __shared__ float avg[128];
    float s = 0.f;
    #pragma unroll 8
    for (int j = 0; j < Jj; ++j) {
        int r = idx[b*Jj + j];
        s += src[((size_t)b*Cc + r)*Dd + tx];
    }
    avg[tx] = s * (1.f/Jj);
    __syncthreads();
    float o = 0.f;
    #pragma unroll 8
    for (int dd = 0; dd < Dd; ++dd)
        o += avg[dd] * W[dd*Dd + tx];
    dst[((size_t)b*Cc + Nn + which)*Dd + tx] = o + bias[tx];
}

// ---------------- precompute uq, uk, consts for one layer ----------------
__global__ void __launch_bounds__(128) precompute_kernel(
    const float* __restrict__ aw, const float* __restrict__ ab,
    const float* __restrict__ sw, const float* __restrict__ sb,
    float* __restrict__ uq, float* __restrict__ uk, float* __restrict__ cv)
{
    int d = threadIdx.x;
    float s1 = 0.f, s2 = 0.f;
    #pragma unroll 8
    for (int e = 0; e < 128; ++e) {
        s1 += aw[d*384 + e]       * sw[e];
        s2 += aw[d*384 + 128 + e] * sw[128 + e];
    }
    uq[d] = s1; uk[d] = s2;
    if (d == 0) {
        float c1 = 0.f, c2 = 0.f;
        for (int e = 0; e < 128; ++e) { c1 += ab[e]*sw[e]; c2 += ab[128+e]*sw[128+e]; }
        cv[0] = c1;
        cv[1] = c2 + sb[0];   // fold score bias into ks const
    }
}

// ---------------- qs/ks per row: one warp per row ----------------
__global__ void __launch_bounds__(256) qsks_kernel(
    const float* __restrict__ feats,
    const float* __restrict__ uq, const float* __restrict__ uk,
    const float* __restrict__ cv,
    float* __restrict__ qs, float* __restrict__ ks)
{
    int warp = threadIdx.x >> 5;
    int lane = threadIdx.x & 31;
    int m = blockIdx.x * 8 + warp;    // grid = BC/8
    float4 f = ((const float4*)(feats + (size_t)m*Dd))[lane];
    float4 q4 = ((const float4*)uq)[lane];
    float4 k4 = ((const float4*)uk)[lane];
    float dq = f.x*q4.x + f.y*q4.y + f.z*q4.z + f.w*q4.w;
    float dk = f.x*k4.x + f.y*k4.y + f.z*k4.z + f.w*k4.w;
    #pragma unroll
    for (int off = 16; off; off >>= 1) {
        dq += __shfl_down_sync(0xffffffffu, dq, off);
        dk += __shfl_down_sync(0xffffffffu, dk, off);
    }
    if (lane == 0) { qs[m] = dq + cv[0]; ks[m] = dk + cv[1]; }
}

// ---------------- generic 128-output SGEMM, 3 A-access modes ----------------
template<int MODE, int KTOT>
__global__ void __launch_bounds__(128) gemm128_kernel(
    const float* __restrict__ A,
    const float* __restrict__ A2,
    const float* __restrict__ W, int ws,
    const float* __restrict__ bias,
    float* __restrict__ out,
    const int* __restrict__ relations,
    int M)
{
    __shared__ float As[32*36];     // transposed: As[kk*36 + i]
    __shared__ float Ws[32*128];
    __shared__ int s_src[3][32];
    __shared__ int s_outrow[32];

    int tx = threadIdx.x;
    int m0 = blockIdx.x * 32;

    if (tx < 32) {
        int m = m0 + tx;
        if (MODE == 1) {
            if (m < M) {
                int b = m / Nn;
                int i = m - b*Nn;
                s_src[0][tx] = b*Cc + i;
                int rp = relations[(size_t)(b*Nn + i)*2 + 0];
                int rs = relations[(size_t)(b*Nn + i)*2 + 1];
                s_src[1][tx] = b*Cc + (rp < 0 ? Nn : rp);
                s_src[2][tx] = b*Cc + (rs < 0 ? Nn + 1 : rs);
                s_outrow[tx] = b*Cc + i;
            } else {
                s_src[0][tx] = 0; s_src[1][tx] = 0; s_src[2][tx] = 0;
                s_outrow[tx] = -1;
            }
        } else {
            s_outrow[tx] = (m < M) ? m : -1;
        }
    }
    __syncthreads();

    float acc[32];
    #pragma unroll
    for (int i = 0; i < 32; ++i) acc[i] = 0.f;

    const int NCHUNK = KTOT / 32;
    for (int kc = 0; kc < NCHUNK; ++kc) {
        int k0 = kc * 32;
        #pragma unroll 8
        for (int kk = 0; kk < 32; ++kk)
            Ws[kk*128 + tx] = W[(size_t)(k0 + kk)*ws + tx];
        int seg  = k0 >> 7;
        int col0 = k0 & 127;
        #pragma unroll
        for (int r = 0; r < 8; ++r) {
            int idx = tx + 128*r;
            int i  = idx >> 5;
            int kk = idx & 31;
            float v;
            if (MODE == 0) {
                v = A[(size_t)(m0 + i)*128 + col0 + kk];
            } else if (MODE == 1) {
                v = A[(size_t)s_src[seg][i]*128 + col0 + kk];
            } else {
                const float* src = seg ? A2 : A;
                v = src[(size_t)(m0 + i)*128 + col0 + kk];
            }
            As[kk*36 + i] = v;
        }
        __syncthreads();
        const float4* As4 = (const float4*)As;
        #pragma unroll 4
        for (int kk = 0; kk < 32; ++kk) {
            float w = Ws[kk*128 + tx];
            #pragma unroll
            for (int i4 = 0; i4 < 8; ++i4) {
                float4 a = As4[kk*9 + i4];
                acc[i4*4+0] += a.x * w;
                acc[i4*4+1] += a.y * w;
                acc[i4*4+2] += a.z * w;
                acc[i4*4+3] += a.w * w;
            }
        }
        __syncthreads();
    }
    float bv = bias[tx];
    #pragma unroll
    for (int i = 0; i < 32; ++i) {
        int orow = s_outrow[i];
        if (orow >= 0) out[(size_t)orow*128 + tx] = acc[i] + bv;
    }
}

// ---------------- fused masked GAT attention, flash-style v2 ----------------
// grid (C/32, B), block 128. 32 i-rows per block, 64-j tiles.
__global__ void __launch_bounds__(128) attn_kernel(
    const float* __restrict__ v,
    const float* __restrict__ qs, const float* __restrict__ ks,
    const float* __restrict__ mask,
    float* __restrict__ weighted)
{
    __shared__ float vs[64*128];      // 32 KB
    __shared__ float ps[64*36];       // ps[jj*36 + i], 4-way padded
    __shared__ float s_qs[32], s_ks[64];
    __shared__ float s_m[32], s_sum[32], s_scale[32];

    int b  = blockIdx.y;
    int i0 = blockIdx.x * 32;
    int tx = threadIdx.x;
    int row = tx >> 2, q = tx & 3;    // 4 lanes per row for reductions

    if (tx < 32) {
        s_qs[tx]  = qs[b*Cc + i0 + tx];
        s_m[tx]   = -1e30f;
        s_sum[tx] = 0.f;
    }

    float acc[32];
    #pragma unroll
    for (int i = 0; i < 32; ++i) acc[i] = 0.f;

    for (int j0 = 0; j0 < Cc; j0 += 64) {
        if (tx < 64) s_ks[tx] = ks[b*Cc + j0 + tx];
        // vectorized v tile load: 64 rows x 32 float4
        {
            const float4* v4 = (const float4*)(v + ((size_t)b*Cc + j0)*128);
            float4* vs4 = (float4*)vs;
            #pragma unroll
            for (int r = 0; r < 16; ++r)
                vs4[r*128 + tx] = v4[r*128 + tx];
        }
        __syncthreads();

        // logits -> ps (mask multiplies the leaky-relu score, pre-softmax)
        #pragma unroll
        for (int r = 0; r < 16; ++r) {
            int e  = r*128 + tx;
            int i  = e >> 6;
            int jj = e & 63;
            int gi = i0 + i;
            int j  = j0 + jj;
            float mval;
            if (gi < Nn && j < Nn) mval = mask[((size_t)b*Nn + gi)*Nn + j];
            else                   mval = (gi == j) ? 1.f : 0.f;
            float s  = s_qs[i] + s_ks[jj];
            float lr = s > 0.f ? s : 0.01f * s;
            ps[jj*36 + i] = lr * mval;
        }
        __syncthreads();

        // per-row running max (4 lanes per row)
        {
            float tm = -1e30f;
            #pragma unroll
            for (int t = 0; t < 16; ++t) tm = fmaxf(tm, ps[(q + 4*t)*36 + row]);
            tm = fmaxf(tm, __shfl_xor_sync(0xffffffffu, tm, 1));
            tm = fmaxf(tm, __shfl_xor_sync(0xffffffffu, tm, 2));
            if (q == 0) {
                float om = s_m[row];
                float nm = fmaxf(om, tm);
                s_scale[row] = __expf(om - nm);
                s_m[row] = nm;
            }
        }
        __syncthreads();

        // exp in place + per-row partial sums
        {
            float m = s_m[row];
            float ss = 0.f;
            #pragma unroll
            for (int t = 0; t < 16; ++t) {
                float e = __expf(ps[(q + 4*t)*36 + row] - m);
                ps[(q + 4*t)*36 + row] = e;
                ss += e;
            }
            ss += __shfl_xor_sync(0xffffffffu, ss, 1);
            ss += __shfl_xor_sync(0xffffffffu, ss, 2);
            if (q == 0) s_sum[row] = s_sum[row]*s_scale[row] + ss;
        }
        __syncthreads();

        #pragma unroll
        for (int i = 0; i < 32; ++i) acc[i] *= s_scale[i];
        #pragma unroll 4
        for (int jj = 0; jj < 64; ++jj) {
            float vv = vs[jj*128 + tx];
            const float4* p4 = (const float4*)(ps + jj*36);
            #pragma unroll
            for (int i4 = 0; i4 < 8; ++i4) {
                float4 a = p4[i4];
                acc[i4*4+0] += a.x * vv;
                acc[i4*4+1] += a.y * vv;
                acc[i4*4+2] += a.z * vv;
                acc[i4*4+3] += a.w * vv;
            }
        }
        __syncthreads();
    }

    #pragma unroll
    for (int i = 0; i < 32; ++i)
        weighted[((size_t)b*Cc + i0 + i)*128 + tx] = acc[i] / s_sum[i];
}

// ---------------- two-phase mean over C rows ----------------
__global__ void __launch_bounds__(128) mean1_kernel(const float* __restrict__ feats,
                                                    float* __restrict__ part)
{
    int b = blockIdx.x, p = blockIdx.y, tx = threadIdx.x;
    float s = 0.f;
    #pragma unroll 8
    for (int i = 0; i < Cc/16; ++i)
        s += feats[((size_t)b*Cc + p*(Cc/16) + i)*128 + tx];
    part[(b*16 + p)*128 + tx] = s;
}

__global__ void __launch_bounds__(128) mean2_kernel(const float* __restrict__ part,
                                                    float* __restrict__ out)
{
    int b = blockIdx.x, tx = threadIdx.x;
    float s = 0.f;
    #pragma unroll
    for (int p = 0; p < 16; ++p)
        s += part[(b*16 + p)*128 + tx];
    out[b*128 + tx] = s * (1.f/Cc);
}

// ---------------- host launcher ----------------
extern "C" void kernel_launch(void* const* d_in, const int* in_sizes, int n_in,
                              void* d_out, int out_size)
{
    const float* ops        = (const float*)d_in[0];
    const float* mask       = (const float*)d_in[1];
    const int*   relations  = (const int*)  d_in[2];
    const int*   begins     = (const int*)  d_in[3];
    const int*   ends       = (const int*)  d_in[4];
    const float* init_bp_w  = (const float*)d_in[5];
    const float* init_bp_b  = (const float*)d_in[6];
    const float* init_ep_w  = (const float*)d_in[7];
    const float* init_ep_b  = (const float*)d_in[8];
    const float* be_bp_w    = (const float*)d_in[9];
    const float* be_bp_b    = (const float*)d_in[10];
    const float* be_ep_w    = (const float*)d_in[11];
    const float* be_ep_b    = (const float*)d_in[12];
    const float* seq_mix_w  = (const float*)d_in[13];
    const float* seq_mix_b  = (const float*)d_in[14];
    const float* attn_w_w   = (const float*)d_in[15];
    const float* attn_w_b   = (const float*)d_in[16];
    const float* score_w    = (const float*)d_in[17];
    const float* score_b    = (const float*)d_in[18];
    const float* attn_out_w = (const float*)d_in[19];
    const float* attn_out_b = (const float*)d_in[20];
    const float* mix_w      = (const float*)d_in[21];
    const float* mix_b      = (const float*)d_in[22];
    float* out = (float*)d_out;

    float *p_f0, *p_f1, *p_v, *p_seq, *p_wt, *p_ao, *p_qs, *p_ks, *p_uq, *p_uk, *p_c, *p_part;
    cudaGetSymbolAddress((void**)&p_f0, g_feats0);
    cudaGetSymbolAddress((void**)&p_f1, g_feats1);
    cudaGetSymbolAddress((void**)&p_v,  g_v);
    cudaGetSymbolAddress((void**)&p_seq, g_seq);
    cudaGetSymbolAddress((void**)&p_wt, g_weighted);
    cudaGetSymbolAddress((void**)&p_ao, g_attnout);
    cudaGetSymbolAddress((void**)&p_qs, g_qs);
    cudaGetSymbolAddress((void**)&p_ks, g_ks);
    cudaGetSymbolAddress((void**)&p_uq, g_uq);
    cudaGetSymbolAddress((void**)&p_uk, g_uk);
    cudaGetSymbolAddress((void**)&p_c,  g_c);
    cudaGetSymbolAddress((void**)&p_part, g_part);

    // init: feats0 = [ops; begin; end]
    copy_ops_kernel<<<(BN*Dd)/256, 256>>>(ops, p_f0);
    begin_end_kernel<<<dim3(Bb, 2), 128>>>(p_f0, begins, ends,
                                           init_bp_w, init_bp_b, init_ep_w, init_ep_b,
                                           p_f0);

    for (int l = 0; l < Ll; ++l) {
        float* cur = (l == 0) ? p_f0 : p_f1;
        float* nxt = (l == 0) ? p_f1 : p_f0;

        precompute_kernel<<<1, 128>>>(attn_w_w + (size_t)l*128*384,
                                      attn_w_b + (size_t)l*384,
                                      score_w + (size_t)l*256,
                                      score_b + l,
                                      p_uq, p_uk, p_c);
        qsks_kernel<<<BC/8, 256>>>(cur, p_uq, p_uk, p_c, p_qs, p_ks);

        // v = feats @ Wv + bv
        gemm128_kernel<0,128><<<BC/32, 128>>>(cur, nullptr,
            attn_w_w + (size_t)l*128*384 + 256, 384,
            attn_w_b + (size_t)l*384 + 256,
            p_v, nullptr, BC);

        // in-layer begin/end -> seq rows N, N+1
        begin_end_kernel<<<dim3(Bb, 2), 128>>>(cur, begins, ends,
            be_bp_w + (size_t)l*128*128, be_bp_b + (size_t)l*128,
            be_ep_w + (size_t)l*128*128, be_ep_b + (size_t)l*128,
            p_seq);

        // mixed = [self, pred, succ] @ seq_mix_w[l] + b  -> seq rows [0, N)
        gemm128_kernel<1,384><<<(BN+31)/32, 128>>>(cur, nullptr,
            seq_mix_w + (size_t)l*384*128, 128,
            seq_mix_b + (size_t)l*128,
            p_seq, relations, BN);

        // fused masked attention -> weighted
        attn_kernel<<<dim3(Cc/32, Bb), 128>>>(p_v, p_qs, p_ks, mask, p_wt);

        // attn_out = weighted @ attn_out_w[l] + b
        gemm128_kernel<0,128><<<BC/32, 128>>>(p_wt, nullptr,
            attn_out_w + (size_t)l*128*128, 128,
            attn_out_b + (size_t)l*128,
            p_ao, nullptr, BC);

        // feats_next = [seq_feats, attn_out] @ mix_w[l] + b
        gemm128_kernel<2,256><<<BC/32, 128>>>(p_seq, p_ao,
            mix_w + (size_t)l*256*128, 128,
            mix_b + (size_t)l*128,
            nxt, nullptr, BC);
    }

    // outputs: mean [B,D] then feats [B,C,D]  (final feats is g_feats0 after L=2)
    mean1_kernel<<<dim3(Bb, 16), 128>>>(p_f0, p_part);
    mean2_kernel<<<Bb, 128>>>(p_part, out);
    copyout_kernel<<<(BC*Dd)/256, 256>>>(p_f0, out + Bb*Dd);
}